// round 2
// baseline (speedup 1.0000x reference)
#include <cuda_runtime.h>

#define HDIM 768
#define DDIM 16
#define MDIM 50
#define HCHUNK 6   // 768 / (32 lanes * 4 floats)

// Precomputed small tensors (allocation-free scratch)
__device__ float g_key[MDIM * DDIM];
__device__ float g_val[MDIM * DDIM];
__device__ float g_WgT[DDIM * HDIM];   // WgT[j][i] = g1[i] * W_down[i][j]
__device__ float g_c1[DDIM];           // sum_i g1[i] * W_down[i][j]
__device__ float g_c2[DDIM];           // sum_i b1[i] * W_down[i][j] + b_down[j]

__global__ void precompute_kernel(
    const float* __restrict__ g1, const float* __restrict__ b1,
    const float* __restrict__ Wd, const float* __restrict__ bd,
    const float* __restrict__ mem,
    const float* __restrict__ Wk, const float* __restrict__ bk,
    const float* __restrict__ Wv, const float* __restrict__ bv)
{
    int tid = threadIdx.x;
    // key / val : [M, D]
    for (int id = tid; id < MDIM * DDIM; id += blockDim.x) {
        int m = id / DDIM, j = id % DDIM;
        float ak = bk[j], av = bv[j];
        #pragma unroll
        for (int k = 0; k < DDIM; k++) {
            float mv = mem[m * DDIM + k];
            ak += mv * Wk[k * DDIM + j];
            av += mv * Wv[k * DDIM + j];
        }
        g_key[id] = ak;
        g_val[id] = av;
    }
    // WgT[j][i]
    for (int id = tid; id < DDIM * HDIM; id += blockDim.x) {
        int j = id / HDIM, i = id % HDIM;
        g_WgT[id] = g1[i] * Wd[i * DDIM + j];
    }
    // c1, c2
    if (tid < DDIM) {
        float c1 = 0.f, c2 = bd[tid];
        for (int i = 0; i < HDIM; i++) {
            c1 += g1[i] * Wd[i * DDIM + tid];
            c2 += b1[i] * Wd[i * DDIM + tid];
        }
        g_c1[tid] = c1;
        g_c2[tid] = c2;
    }
}

__global__ __launch_bounds__(256, 2) void fused_kernel(
    const float* __restrict__ x,
    const float* __restrict__ Wup,   // [D, H] row-major
    const float* __restrict__ bup,   // [H]
    const float* __restrict__ g2, const float* __restrict__ b2,
    const float* __restrict__ g3, const float* __restrict__ b3,
    float* __restrict__ out, int ntok)
{
    extern __shared__ float smem[];
    float* sWgT = smem;                        // D*H
    float* sWup = sWgT + DDIM * HDIM;          // D*H
    float* sKey = sWup + DDIM * HDIM;          // M*D
    float* sVal = sKey + MDIM * DDIM;          // M*D
    float* sBup = sVal + MDIM * DDIM;          // H
    float* sC1  = sBup + HDIM;                 // D each below
    float* sC2  = sC1 + DDIM;
    float* sG2  = sC2 + DDIM;
    float* sB2  = sG2 + DDIM;
    float* sG3  = sB2 + DDIM;
    float* sB3  = sG3 + DDIM;

    int tid = threadIdx.x;
    for (int i = tid; i < DDIM * HDIM; i += 256) {
        sWgT[i] = g_WgT[i];
        sWup[i] = Wup[i];
    }
    for (int i = tid; i < MDIM * DDIM; i += 256) {
        sKey[i] = g_key[i];
        sVal[i] = g_val[i];
    }
    for (int i = tid; i < HDIM; i += 256) sBup[i] = bup[i];
    if (tid < DDIM) {
        sC1[tid] = g_c1[tid]; sC2[tid] = g_c2[tid];
        sG2[tid] = g2[tid];   sB2[tid] = b2[tid];
        sG3[tid] = g3[tid];   sB3[tid] = b3[tid];
    }
    __syncthreads();

    const int lane = tid & 31;
    const int warp = tid >> 5;
    const int gw = blockIdx.x * 8 + warp;
    const int stride = gridDim.x * 8;

    for (int tok = gw; tok < ntok; tok += stride) {
        const float* xr = x + (size_t)tok * HDIM;

        // ---- pass 1: sums for LN1 + down-projection dots (fused, single read of x)
        float s0 = 0.f, s1 = 0.f;
        float t[DDIM];
        #pragma unroll
        for (int j = 0; j < DDIM; j++) t[j] = 0.f;

        #pragma unroll
        for (int c = 0; c < HCHUNK; c++) {
            int base = c * 128 + lane * 4;
            float4 xv = *reinterpret_cast<const float4*>(xr + base);
            s0 += xv.x + xv.y + xv.z + xv.w;
            s1 += xv.x * xv.x + xv.y * xv.y + xv.z * xv.z + xv.w * xv.w;
            #pragma unroll
            for (int j = 0; j < DDIM; j++) {
                float4 wv = *reinterpret_cast<const float4*>(sWgT + j * HDIM + base);
                t[j] += xv.x * wv.x + xv.y * wv.y + xv.z * wv.z + xv.w * wv.w;
            }
        }
        // butterfly reduce the 18 sums (all lanes end with full values)
        #pragma unroll
        for (int off = 16; off > 0; off >>= 1) {
            s0 += __shfl_xor_sync(0xffffffffu, s0, off);
            s1 += __shfl_xor_sync(0xffffffffu, s1, off);
            #pragma unroll
            for (int j = 0; j < DDIM; j++)
                t[j] += __shfl_xor_sync(0xffffffffu, t[j], off);
        }

        float mean = s0 * (1.f / HDIM);
        float var  = s1 * (1.f / HDIM) - mean * mean;
        float rstd = rsqrtf(var + 1e-12f);

        // ---- d = LN1(x) @ W_down + b_down   (via folded constants)
        float dv[DDIM];
        float dsum = 0.f;
        #pragma unroll
        for (int j = 0; j < DDIM; j++) {
            dv[j] = rstd * (t[j] - mean * sC1[j]) + sC2[j];
            dsum += dv[j];
        }
        // ---- LN2 (exact, in registers, redundant per lane)
        float dmean = dsum * (1.f / DDIM);
        float dvar = 0.f;
        #pragma unroll
        for (int j = 0; j < DDIM; j++) {
            float df = dv[j] - dmean;
            dvar += df * df;
        }
        float drs = rsqrtf(dvar * (1.f / DDIM) + 1e-12f);
        float q[DDIM];
        #pragma unroll
        for (int j = 0; j < DDIM; j++)
            q[j] = (dv[j] - dmean) * drs * sG2[j] + sB2[j];

        // ---- attention over M=50 memory slots: lane handles m=lane and m=lane+32
        int m1 = lane + 32;
        bool h1 = (m1 < MDIM);
        float sc0 = 0.f, sc1 = -INFINITY;
        {
            const float* kr = sKey + lane * DDIM;
            float a = 0.f;
            #pragma unroll
            for (int j = 0; j < DDIM; j++) a += q[j] * kr[j];
            sc0 = a;
        }
        if (h1) {
            const float* kr = sKey + m1 * DDIM;
            float a = 0.f;
            #pragma unroll
            for (int j = 0; j < DDIM; j++) a += q[j] * kr[j];
            sc1 = a;
        }
        float mx = fmaxf(sc0, sc1);
        #pragma unroll
        for (int off = 16; off > 0; off >>= 1)
            mx = fmaxf(mx, __shfl_xor_sync(0xffffffffu, mx, off));
        float e0 = __expf(sc0 - mx);
        float e1 = h1 ? __expf(sc1 - mx) : 0.f;
        float es = e0 + e1;
        #pragma unroll
        for (int off = 16; off > 0; off >>= 1)
            es += __shfl_xor_sync(0xffffffffu, es, off);
        float inv = 1.f / es;

        // mem_out = softmax @ val
        float mo[DDIM];
        {
            const float* v0 = sVal + lane * DDIM;
            #pragma unroll
            for (int j = 0; j < DDIM; j++) mo[j] = e0 * v0[j];
        }
        if (h1) {
            const float* v1 = sVal + m1 * DDIM;
            #pragma unroll
            for (int j = 0; j < DDIM; j++) mo[j] += e1 * v1[j];
        }
        #pragma unroll
        for (int off = 16; off > 0; off >>= 1) {
            #pragma unroll
            for (int j = 0; j < DDIM; j++)
                mo[j] += __shfl_xor_sync(0xffffffffu, mo[j], off);
        }

        // ---- LN3
        float msum = 0.f;
        #pragma unroll
        for (int j = 0; j < DDIM; j++) {
            mo[j] *= inv;
            msum += mo[j];
        }
        float mmean = msum * (1.f / DDIM);
        float mvar = 0.f;
        #pragma unroll
        for (int j = 0; j < DDIM; j++) {
            float df = mo[j] - mmean;
            mvar += df * df;
        }
        float mrs = rsqrtf(mvar * (1.f / DDIM) + 1e-12f);
        float memn[DDIM];
        #pragma unroll
        for (int j = 0; j < DDIM; j++)
            memn[j] = (mo[j] - mmean) * mrs * sG3[j] + sB3[j];

        // ---- up-projection: out = memn @ W_up + b_up
        float* orow = out + (size_t)tok * HDIM;
        #pragma unroll
        for (int c = 0; c < HCHUNK; c++) {
            int base = c * 128 + lane * 4;
            float4 o;
            o.x = sBup[base + 0];
            o.y = sBup[base + 1];
            o.z = sBup[base + 2];
            o.w = sBup[base + 3];
            #pragma unroll
            for (int j = 0; j < DDIM; j++) {
                float4 wv = *reinterpret_cast<const float4*>(sWup + j * HDIM + base);
                float mj = memn[j];
                o.x += mj * wv.x;
                o.y += mj * wv.y;
                o.z += mj * wv.z;
                o.w += mj * wv.w;
            }
            *reinterpret_cast<float4*>(orow + base) = o;
        }
    }
}

extern "C" void kernel_launch(void* const* d_in, const int* in_sizes, int n_in,
                              void* d_out, int out_size)
{
    const float* x   = (const float*)d_in[0];
    const float* g1  = (const float*)d_in[1];
    const float* b1  = (const float*)d_in[2];
    const float* Wd  = (const float*)d_in[3];
    const float* bd  = (const float*)d_in[4];
    const float* g2  = (const float*)d_in[5];
    const float* b2  = (const float*)d_in[6];
    const float* mem = (const float*)d_in[7];
    const float* Wk  = (const float*)d_in[8];
    const float* bk  = (const float*)d_in[9];
    const float* Wv  = (const float*)d_in[10];
    const float* bv  = (const float*)d_in[11];
    const float* g3  = (const float*)d_in[12];
    const float* b3  = (const float*)d_in[13];
    const float* Wup = (const float*)d_in[14];
    const float* bup = (const float*)d_in[15];
    float* out = (float*)d_out;

    int ntok = in_sizes[0] / HDIM;

    precompute_kernel<<<1, 256>>>(g1, b1, Wd, bd, mem, Wk, bk, Wv, bv);

    size_t smembytes = (size_t)(2 * DDIM * HDIM + 2 * MDIM * DDIM + HDIM + 6 * DDIM) * sizeof(float);
    cudaFuncSetAttribute(fused_kernel, cudaFuncAttributeMaxDynamicSharedMemorySize, (int)smembytes);
    fused_kernel<<<296, 256, smembytes>>>(x, Wup, bup, g2, b2, g3, b3, out, ntok);
}

// round 4
// speedup vs baseline: 2.5852x; 2.5852x over previous
#include <cuda_runtime.h>

#define HDIM 768
#define DDIM 16
#define MDIM 50
#define NJ2  8            // DDIM/2 packed pairs
#define HC   12           // 768 / (32 lanes * 2 cols)
#define TTOK 4            // tokens per warp per iteration
#define NBLK 296
#define NWRP 8            // warps per block

// ---------- packed f32x2 helpers ----------
__device__ __forceinline__ unsigned long long ffma2(unsigned long long a,
                                                    unsigned long long b,
                                                    unsigned long long c) {
    unsigned long long d;
    asm("fma.rn.f32x2 %0, %1, %2, %3;" : "=l"(d) : "l"(a), "l"(b), "l"(c));
    return d;
}
__device__ __forceinline__ unsigned long long pack2(float lo, float hi) {
    unsigned long long r;
    asm("mov.b64 %0, {%1, %2};" : "=l"(r) : "f"(lo), "f"(hi));
    return r;
}
__device__ __forceinline__ unsigned long long packbb(float v) {
    unsigned long long r;
    asm("mov.b64 %0, {%1, %1};" : "=l"(r) : "f"(v));
    return r;
}
__device__ __forceinline__ void unpack2(unsigned long long v, float& lo, float& hi) {
    asm("mov.b64 {%0, %1}, %2;" : "=f"(lo), "=f"(hi) : "l"(v));
}

// ---------- precomputed tensors (device globals; allocation-free) ----------
// W2d[j2*HDIM + i] = ( g1[i]*Wd[i][2j2] , g1[i]*Wd[i][2j2+1] )   packed pairs
// W2u[j2*HDIM + i] = ( Wup[2j2][i]      , Wup[2j2+1][i] )
__device__ unsigned long long g_W2d[NJ2 * HDIM];
__device__ unsigned long long g_W2u[NJ2 * HDIM];
__device__ float g_key[MDIM * DDIM];
__device__ float g_val[MDIM * DDIM];
__device__ float g_c1[DDIM];
__device__ float g_c2[DDIM];

__global__ void precompute_kernel(
    const float* __restrict__ g1, const float* __restrict__ b1,
    const float* __restrict__ Wd, const float* __restrict__ bd,
    const float* __restrict__ mem,
    const float* __restrict__ Wk, const float* __restrict__ bk,
    const float* __restrict__ Wv, const float* __restrict__ bv,
    const float* __restrict__ Wup)
{
    int gtid = blockIdx.x * blockDim.x + threadIdx.x;
    int gstr = gridDim.x * blockDim.x;

    // packed down/up weights
    for (int id = gtid; id < NJ2 * HDIM; id += gstr) {
        int j2 = id / HDIM, i = id % HDIM;
        float a = g1[i] * Wd[i * DDIM + 2 * j2];
        float b = g1[i] * Wd[i * DDIM + 2 * j2 + 1];
        g_W2d[id] = pack2(a, b);
        g_W2u[id] = pack2(Wup[(2 * j2) * HDIM + i], Wup[(2 * j2 + 1) * HDIM + i]);
    }
    // key / val : [M, D]
    for (int id = gtid; id < MDIM * DDIM; id += gstr) {
        int m = id / DDIM, j = id % DDIM;
        float ak = bk[j], av = bv[j];
        #pragma unroll
        for (int k = 0; k < DDIM; k++) {
            float mv = mem[m * DDIM + k];
            ak += mv * Wk[k * DDIM + j];
            av += mv * Wv[k * DDIM + j];
        }
        g_key[id] = ak;
        g_val[id] = av;
    }
    // c1, c2 : one warp per j (blocks 0..1)
    if (blockIdx.x < 2) {
        int warp = threadIdx.x >> 5, lane = threadIdx.x & 31;
        int j = blockIdx.x * 8 + warp;
        if (j < DDIM) {
            float c1 = 0.f, c2 = 0.f;
            for (int i = lane; i < HDIM; i += 32) {
                float w = Wd[i * DDIM + j];
                c1 += g1[i] * w;
                c2 += b1[i] * w;
            }
            #pragma unroll
            for (int off = 16; off > 0; off >>= 1) {
                c1 += __shfl_xor_sync(0xffffffffu, c1, off);
                c2 += __shfl_xor_sync(0xffffffffu, c2, off);
            }
            if (lane == 0) { g_c1[j] = c1; g_c2[j] = c2 + bd[j]; }
        }
    }
}

__global__ __launch_bounds__(256, 2) void fused_kernel(
    const float* __restrict__ x,
    const float* __restrict__ bup,
    const float* __restrict__ g2, const float* __restrict__ b2,
    const float* __restrict__ g3, const float* __restrict__ b3,
    float* __restrict__ out, int ntok)
{
    extern __shared__ unsigned long long smemll[];
    unsigned long long* sW2d = smemll;                    // NJ2*HDIM ull
    unsigned long long* sW2u = sW2d + NJ2 * HDIM;         // NJ2*HDIM ull
    float* sKey = (float*)(sW2u + NJ2 * HDIM);            // M*D
    float* sVal = sKey + MDIM * DDIM;                     // M*D
    float* sBup = sVal + MDIM * DDIM;                     // H
    float* sC1  = sBup + HDIM;
    float* sC2  = sC1 + DDIM;
    float* sG2  = sC2 + DDIM;
    float* sB2  = sG2 + DDIM;
    float* sG3  = sB2 + DDIM;
    float* sB3  = sG3 + DDIM;

    const int tid = threadIdx.x;
    for (int i = tid; i < NJ2 * HDIM; i += 256) {
        sW2d[i] = g_W2d[i];
        sW2u[i] = g_W2u[i];
    }
    for (int i = tid; i < MDIM * DDIM; i += 256) {
        sKey[i] = g_key[i];
        sVal[i] = g_val[i];
    }
    for (int i = tid; i < HDIM; i += 256) sBup[i] = bup[i];
    if (tid < DDIM) {
        sC1[tid] = g_c1[tid]; sC2[tid] = g_c2[tid];
        sG2[tid] = g2[tid];   sB2[tid] = b2[tid];
        sG3[tid] = g3[tid];   sB3[tid] = b3[tid];
    }
    __syncthreads();

    const int lane = tid & 31;
    const int warp = tid >> 5;
    const int gw = blockIdx.x * NWRP + warp;
    const int gstride = NBLK * NWRP * TTOK;

    for (int tok0 = gw * TTOK; tok0 < ntok; tok0 += gstride) {
        // clamp rows for safety on ragged tails
        int row[TTOK];
        #pragma unroll
        for (int tt = 0; tt < TTOK; tt++) {
            int r = tok0 + tt;
            row[tt] = (r < ntok) ? r : (ntok - 1);
        }
        const float* xr0 = x + (size_t)row[0] * HDIM;
        const float* xr1 = x + (size_t)row[1] * HDIM;
        const float* xr2 = x + (size_t)row[2] * HDIM;
        const float* xr3 = x + (size_t)row[3] * HDIM;

        // ---------------- pass 1: LN1 stats + packed down-projection ----------------
        unsigned long long t2[TTOK][NJ2];
        float s0[TTOK], s1[TTOK];
        #pragma unroll
        for (int tt = 0; tt < TTOK; tt++) {
            s0[tt] = 0.f; s1[tt] = 0.f;
            #pragma unroll
            for (int j2 = 0; j2 < NJ2; j2++) t2[tt][j2] = 0ull;
        }

        #pragma unroll
        for (int c = 0; c < HC; c++) {
            const int i0 = c * 64 + lane * 2;
            float2 xv0 = *reinterpret_cast<const float2*>(xr0 + i0);
            float2 xv1 = *reinterpret_cast<const float2*>(xr1 + i0);
            float2 xv2 = *reinterpret_cast<const float2*>(xr2 + i0);
            float2 xv3 = *reinterpret_cast<const float2*>(xr3 + i0);

            s0[0] += xv0.x + xv0.y;  s1[0] += xv0.x * xv0.x + xv0.y * xv0.y;
            s0[1] += xv1.x + xv1.y;  s1[1] += xv1.x * xv1.x + xv1.y * xv1.y;
            s0[2] += xv2.x + xv2.y;  s1[2] += xv2.x * xv2.x + xv2.y * xv2.y;
            s0[3] += xv3.x + xv3.y;  s1[3] += xv3.x * xv3.x + xv3.y * xv3.y;

            unsigned long long xp[TTOK][2];
            xp[0][0] = packbb(xv0.x); xp[0][1] = packbb(xv0.y);
            xp[1][0] = packbb(xv1.x); xp[1][1] = packbb(xv1.y);
            xp[2][0] = packbb(xv2.x); xp[2][1] = packbb(xv2.y);
            xp[3][0] = packbb(xv3.x); xp[3][1] = packbb(xv3.y);

            #pragma unroll
            for (int j2 = 0; j2 < NJ2; j2++) {
                ulonglong2 w = *reinterpret_cast<const ulonglong2*>(sW2d + j2 * HDIM + i0);
                #pragma unroll
                for (int tt = 0; tt < TTOK; tt++) {
                    t2[tt][j2] = ffma2(xp[tt][0], w.x, t2[tt][j2]);
                    t2[tt][j2] = ffma2(xp[tt][1], w.y, t2[tt][j2]);
                }
            }
        }

        // warp reductions (all lanes get full sums)
        #pragma unroll
        for (int off = 16; off > 0; off >>= 1) {
            #pragma unroll
            for (int tt = 0; tt < TTOK; tt++) {
                s0[tt] += __shfl_xor_sync(0xffffffffu, s0[tt], off);
                s1[tt] += __shfl_xor_sync(0xffffffffu, s1[tt], off);
                #pragma unroll
                for (int j2 = 0; j2 < NJ2; j2++) {
                    unsigned long long o = __shfl_xor_sync(0xffffffffu, t2[tt][j2], off);
                    float al, ah, bl, bh;
                    unpack2(t2[tt][j2], al, ah);
                    unpack2(o, bl, bh);
                    t2[tt][j2] = pack2(al + bl, ah + bh);
                }
            }
        }

        // ---------------- middle: LN1-fold, LN2, attention, LN3 (per token) ----------------
        unsigned long long q2[TTOK][NJ2];   // packed memn for up-projection
        #pragma unroll
        for (int tt = 0; tt < TTOK; tt++) {
            float mean = s0[tt] * (1.f / HDIM);
            float var  = s1[tt] * (1.f / HDIM) - mean * mean;
            float rstd = rsqrtf(var + 1e-12f);

            float dv[DDIM];
            float dsum = 0.f;
            #pragma unroll
            for (int j2 = 0; j2 < NJ2; j2++) {
                float tl, th;
                unpack2(t2[tt][j2], tl, th);
                float a = rstd * (tl - mean * sC1[2 * j2])     + sC2[2 * j2];
                float b = rstd * (th - mean * sC1[2 * j2 + 1]) + sC2[2 * j2 + 1];
                dv[2 * j2] = a; dv[2 * j2 + 1] = b;
                dsum += a + b;
            }
            float dmean = dsum * (1.f / DDIM);
            float dvar = 0.f;
            #pragma unroll
            for (int j = 0; j < DDIM; j++) { float df = dv[j] - dmean; dvar += df * df; }
            float drs = rsqrtf(dvar * (1.f / DDIM) + 1e-12f);
            float q[DDIM];
            #pragma unroll
            for (int j = 0; j < DDIM; j++)
                q[j] = (dv[j] - dmean) * drs * sG2[j] + sB2[j];

            // attention over M=50 slots: lane handles m=lane, m=lane+32
            int m1 = lane + 32;
            bool h1 = (m1 < MDIM);
            float sc0 = 0.f, sc1 = -INFINITY;
            {
                const float* kr = sKey + lane * DDIM;
                float a = 0.f;
                #pragma unroll
                for (int j = 0; j < DDIM; j++) a += q[j] * kr[j];
                sc0 = a;
            }
            if (h1) {
                const float* kr = sKey + m1 * DDIM;
                float a = 0.f;
                #pragma unroll
                for (int j = 0; j < DDIM; j++) a += q[j] * kr[j];
                sc1 = a;
            }
            float mx = fmaxf(sc0, sc1);
            #pragma unroll
            for (int off = 16; off > 0; off >>= 1)
                mx = fmaxf(mx, __shfl_xor_sync(0xffffffffu, mx, off));
            float e0 = __expf(sc0 - mx);
            float e1 = h1 ? __expf(sc1 - mx) : 0.f;
            float es = e0 + e1;
            #pragma unroll
            for (int off = 16; off > 0; off >>= 1)
                es += __shfl_xor_sync(0xffffffffu, es, off);
            float inv = 1.f / es;

            float mo[DDIM];
            {
                const float* v0 = sVal + lane * DDIM;
                #pragma unroll
                for (int j = 0; j < DDIM; j++) mo[j] = e0 * v0[j];
            }
            if (h1) {
                const float* v1 = sVal + m1 * DDIM;
                #pragma unroll
                for (int j = 0; j < DDIM; j++) mo[j] += e1 * v1[j];
            }
            #pragma unroll
            for (int off = 16; off > 0; off >>= 1) {
                #pragma unroll
                for (int j = 0; j < DDIM; j++)
                    mo[j] += __shfl_xor_sync(0xffffffffu, mo[j], off);
            }

            float msum = 0.f;
            #pragma unroll
            for (int j = 0; j < DDIM; j++) { mo[j] *= inv; msum += mo[j]; }
            float mmean = msum * (1.f / DDIM);
            float mvar = 0.f;
            #pragma unroll
            for (int j = 0; j < DDIM; j++) { float df = mo[j] - mmean; mvar += df * df; }
            float mrs = rsqrtf(mvar * (1.f / DDIM) + 1e-12f);
            #pragma unroll
            for (int j2 = 0; j2 < NJ2; j2++) {
                float a = (mo[2 * j2]     - mmean) * mrs * sG3[2 * j2]     + sB3[2 * j2];
                float b = (mo[2 * j2 + 1] - mmean) * mrs * sG3[2 * j2 + 1] + sB3[2 * j2 + 1];
                q2[tt][j2] = pack2(a, b);
            }
        }

        // ---------------- up-projection: out = memn @ W_up + b_up ----------------
        bool st[TTOK];
        #pragma unroll
        for (int tt = 0; tt < TTOK; tt++) st[tt] = (tok0 + tt) < ntok;
        float* or0 = out + (size_t)row[0] * HDIM;
        float* or1 = out + (size_t)row[1] * HDIM;
        float* or2 = out + (size_t)row[2] * HDIM;
        float* or3 = out + (size_t)row[3] * HDIM;

        #pragma unroll
        for (int c = 0; c < HC; c++) {
            const int i0 = c * 64 + lane * 2;
            unsigned long long a0[TTOK], a1[TTOK];
            #pragma unroll
            for (int tt = 0; tt < TTOK; tt++) { a0[tt] = 0ull; a1[tt] = 0ull; }

            #pragma unroll
            for (int j2 = 0; j2 < NJ2; j2++) {
                ulonglong2 w = *reinterpret_cast<const ulonglong2*>(sW2u + j2 * HDIM + i0);
                #pragma unroll
                for (int tt = 0; tt < TTOK; tt++) {
                    a0[tt] = ffma2(q2[tt][j2], w.x, a0[tt]);
                    a1[tt] = ffma2(q2[tt][j2], w.y, a1[tt]);
                }
            }
            float bx = sBup[i0], by = sBup[i0 + 1];
            #pragma unroll
            for (int tt = 0; tt < TTOK; tt++) {
                float l0, h0, l1, h1v;
                unpack2(a0[tt], l0, h0);
                unpack2(a1[tt], l1, h1v);
                float2 o;
                o.x = l0 + h0 + bx;
                o.y = l1 + h1v + by;
                if (st[tt]) {
                    float* orow = (tt == 0) ? or0 : (tt == 1) ? or1 : (tt == 2) ? or2 : or3;
                    *reinterpret_cast<float2*>(orow + i0) = o;
                }
            }
        }
    }
}

extern "C" void kernel_launch(void* const* d_in, const int* in_sizes, int n_in,
                              void* d_out, int out_size)
{
    const float* x   = (const float*)d_in[0];
    const float* g1  = (const float*)d_in[1];
    const float* b1  = (const float*)d_in[2];
    const float* Wd  = (const float*)d_in[3];
    const float* bd  = (const float*)d_in[4];
    const float* g2  = (const float*)d_in[5];
    const float* b2  = (const float*)d_in[6];
    const float* mem = (const float*)d_in[7];
    const float* Wk  = (const float*)d_in[8];
    const float* bk  = (const float*)d_in[9];
    const float* Wv  = (const float*)d_in[10];
    const float* bv  = (const float*)d_in[11];
    const float* g3  = (const float*)d_in[12];
    const float* b3  = (const float*)d_in[13];
    const float* Wup = (const float*)d_in[14];
    const float* bup = (const float*)d_in[15];
    float* out = (float*)d_out;

    int ntok = in_sizes[0] / HDIM;

    precompute_kernel<<<80, 256>>>(g1, b1, Wd, bd, mem, Wk, bk, Wv, bv, Wup);

    size_t smembytes = (size_t)(2 * NJ2 * HDIM) * sizeof(unsigned long long)
                     + (size_t)(2 * MDIM * DDIM + HDIM + 6 * DDIM) * sizeof(float);
    cudaFuncSetAttribute(fused_kernel, cudaFuncAttributeMaxDynamicSharedMemorySize, (int)smembytes);
    fused_kernel<<<NBLK, 256, smembytes>>>(x, bup, g2, b2, g3, b3, out, ntok);
}